// round 12
// baseline (speedup 1.0000x reference)
#include <cuda_runtime.h>
#include <cstdint>

// Leaky RNN: x_t = 0.9*x_{t-1} + 0.1*(u@Win + tanh(x_{t-1})@Wrec + brec) + q_t
//            z_t = tanh(x_t)@Wout + bout
// T=1024, B=64, NIN=32, N=256, NOUT=16.
//
// Pre : g[t,b,n] = noise + 0.1*(u@Win + brec)
// A   : 128 CTAs = 64 batches x 2 cluster ranks (k-split halves).
//       Thread (w, l): ksub=l&3, rl=w*8+(l>>2). Dots 4 cols
//       {own rl, own rl+64, peer rl, peer rl+64} over k-sub [128rho+32ksub,+32).
//       4-ksub partials reduced IN-WARP (2x shfl_xor) -- no smem reduction, no
//       extra sync. Reducer lanes (ksub==0) own 2 state cols: send 2 peer sums
//       (1x st.shared::cluster.v2 + 1 arrive, 64 msgs/step), wait late, update.
//       ONE __syncthreads per step.
// B   : outputs = tanh(states) @ Wout + bout.

#define T_STEPS 1024
#define B_SZ    64
#define N_IN    32
#define N_HID   256
#define N_OUT   16

typedef unsigned long long ull;

__device__ float g_buf[T_STEPS * B_SZ * N_HID];

__device__ __forceinline__ void ffma2(ull& acc, ull a, ull b) {
    asm("fma.rn.f32x2 %0, %1, %2, %0;" : "+l"(acc) : "l"(a), "l"(b));
}
__device__ __forceinline__ ull pack2(float lo, float hi) {
    ull r; asm("mov.b64 %0, {%1, %2};" : "=l"(r) : "f"(lo), "f"(hi)); return r;
}
__device__ __forceinline__ float hadd2(ull a) {
    float lo, hi; asm("mov.b64 {%0, %1}, %2;" : "=f"(lo), "=f"(hi) : "l"(a));
    return lo + hi;
}
__device__ __forceinline__ float ftanh(float x) {
    float e = __expf(2.0f * x);
    return 1.0f - __fdividef(2.0f, e + 1.0f);
}
__device__ __forceinline__ unsigned mapa32(unsigned laddr, unsigned peer) {
    unsigned r;
    asm volatile("mapa.shared::cluster.u32 %0, %1, %2;" : "=r"(r) : "r"(laddr), "r"(peer));
    return r;
}
__device__ __forceinline__ void st_remote_v2(unsigned addr, float a, float bb) {
    asm volatile("st.shared::cluster.v2.f32 [%0], {%1, %2};"
                 :: "r"(addr), "f"(a), "f"(bb) : "memory");
}
__device__ __forceinline__ void arrive_remote(unsigned addr) {
    asm volatile("mbarrier.arrive.release.cluster.shared::cluster.b64 _, [%0];"
                 :: "r"(addr) : "memory");
}
__device__ __forceinline__ void mbar_wait_cluster(unsigned addr, unsigned parity) {
    unsigned done;
    do {
        asm volatile(
            "{\n\t.reg .pred P;\n\t"
            "mbarrier.try_wait.parity.acquire.cluster.shared::cta.b64 P, [%1], %2, 0x989680;\n\t"
            "selp.b32 %0, 1, 0, P;\n\t}"
            : "=r"(done) : "r"(addr), "r"(parity) : "memory");
    } while (!done);
}
#define CLUSTER_SYNC() do { \
    asm volatile("barrier.cluster.arrive.aligned;" ::: "memory"); \
    asm volatile("barrier.cluster.wait.aligned;"   ::: "memory"); } while (0)

// ---------------- Pre-kernel: g = noise + 0.1*(u@Win + brec) ----------------
__global__ void __launch_bounds__(256)
uproj_kernel(const float* __restrict__ inputs,   // [T*B, NIN]
             const float* __restrict__ noise,    // [T*B, N]
             const float* __restrict__ Win,      // [NIN, N]
             const float* __restrict__ brec)     // [N]
{
    __shared__ float su[8][N_IN];
    const int tid = threadIdx.x;

    float w_in[N_IN];
#pragma unroll
    for (int i = 0; i < N_IN; ++i) w_in[i] = Win[i * N_HID + tid];
    const float br = brec[tid];

    const int row0 = blockIdx.x * 8;
    su[tid >> 5][tid & 31] = inputs[row0 * N_IN + tid];
    __syncthreads();

#pragma unroll
    for (int rr = 0; rr < 8; ++rr) {
        const int row = row0 + rr;
        float acc = br;
#pragma unroll
        for (int i = 0; i < N_IN; ++i) acc = fmaf(su[rr][i], w_in[i], acc);
        g_buf[row * N_HID + tid] = noise[row * N_HID + tid] + 0.1f * acc;
    }
}

// ---------------- Kernel A: recurrence (shuffle-reduce, v2 sum exchange) ----------------
__global__ void __launch_bounds__(256, 1) __cluster_dims__(2, 1, 1)
rnn_step_kernel(const float* __restrict__ x0,     // [B,N]
                const float* __restrict__ Wrec,   // [N,N]
                float* __restrict__ states)       // [T,B,N]
{
    __shared__ __align__(16) float r_s[2][128];    // own-half r, dbl-buffered
    __shared__ __align__(16) float inbox[2][128];  // peer sums [p][2*rl + {0,1}]
    __shared__ __align__(8)  ull   mbar[2];

    const int tid = threadIdx.x;
    const int b   = blockIdx.x >> 1;
    const unsigned rho = blockIdx.x & 1u;
    const int w    = tid >> 5;
    const int l    = tid & 31;
    const int ksub = l & 3;              // k sub-slice 0..3
    const int rl   = w * 8 + (l >> 2);   // reducer/column index 0..63

    const int ownBase  = (int)rho * 128;
    const int peerBase = ((int)rho ^ 1) * 128;
    const int kbase    = ownBase + 32 * ksub;    // own k-half only

    // weights: 4 cols x 32 k = 64 ull
    ull W0[16], W1[16], W2[16], W3[16];
#pragma unroll
    for (int i = 0; i < 16; ++i) {
        const int k = kbase + 2 * i;
        W0[i] = pack2(Wrec[k * N_HID + ownBase + rl],
                      Wrec[(k + 1) * N_HID + ownBase + rl]);
        W1[i] = pack2(Wrec[k * N_HID + ownBase + rl + 64],
                      Wrec[(k + 1) * N_HID + ownBase + rl + 64]);
        W2[i] = pack2(Wrec[k * N_HID + peerBase + rl],
                      Wrec[(k + 1) * N_HID + peerBase + rl]);
        W3[i] = pack2(Wrec[k * N_HID + peerBase + rl + 64],
                      Wrec[(k + 1) * N_HID + peerBase + rl + 64]);
    }

    if (tid == 0) {
        asm volatile("mbarrier.init.shared.b64 [%0], %1;"
                     :: "r"((unsigned)__cvta_generic_to_shared(&mbar[0])), "r"(64) : "memory");
        asm volatile("mbarrier.init.shared.b64 [%0], %1;"
                     :: "r"((unsigned)__cvta_generic_to_shared(&mbar[1])), "r"(64) : "memory");
    }

    // remote targets (used by reducer lanes): peer inbox[0][2*rl], peer mbar
    const unsigned r_inbox = mapa32(
        (unsigned)__cvta_generic_to_shared(&inbox[0][2 * rl]), rho ^ 1u);
    const unsigned r_mbar = mapa32(
        (unsigned)__cvta_generic_to_shared(&mbar[0]), rho ^ 1u);

    // reducer lanes own state for cols ownBase+rl, ownBase+rl+64
    float xs0 = 0.0f, xs1 = 0.0f, gr0 = 0.0f, gr1 = 0.0f;
    const float* gp0 = g_buf + b * N_HID + ownBase + rl;
    const float* gp1 = gp0 + 64;
    float* sp0 = states + b * N_HID + ownBase + rl;
    float* sp1 = sp0 + 64;

    if (ksub == 0) {
        xs0 = x0[b * N_HID + ownBase + rl];
        xs1 = x0[b * N_HID + ownBase + rl + 64];
        r_s[0][rl]      = ftanh(xs0);
        r_s[0][rl + 64] = ftanh(xs1);
        gr0 = gp0[0];
        gr1 = gp1[0];
    }

    __syncthreads();
    CLUSTER_SYNC();                      // peer mbar init visible

    const unsigned mb0 = (unsigned)__cvta_generic_to_shared(&mbar[0]);
    int ph0 = 0, ph1 = 0;

#pragma unroll 1
    for (int t = 0; t < T_STEPS; ++t) {
        const int p    = t & 1;
        const int nbuf = p ^ 1;

        // ---- dot over own 32-k sub-slice (8 broadcast LDS.128, 64 FFMA2) ----
        const ulonglong2* rp = reinterpret_cast<const ulonglong2*>(&r_s[p][32 * ksub]);
        ulonglong2 rv[8];
#pragma unroll
        for (int q = 0; q < 8; ++q) rv[q] = rp[q];

        ull a0 = 0, a1 = 0, a2 = 0, a3 = 0;
#pragma unroll
        for (int q = 0; q < 8; ++q) {
            ffma2(a0, W0[2 * q], rv[q].x);  ffma2(a0, W0[2 * q + 1], rv[q].y);
            ffma2(a1, W1[2 * q], rv[q].x);  ffma2(a1, W1[2 * q + 1], rv[q].y);
            ffma2(a2, W2[2 * q], rv[q].x);  ffma2(a2, W2[2 * q + 1], rv[q].y);
            ffma2(a3, W3[2 * q], rv[q].x);  ffma2(a3, W3[2 * q + 1], rv[q].y);
        }
        float f0 = hadd2(a0), f1 = hadd2(a1), f2 = hadd2(a2), f3 = hadd2(a3);

        // ---- in-warp ksub reduction (lanes 4q..4q+3 share the same columns) ----
        f0 += __shfl_xor_sync(0xffffffffu, f0, 1);
        f0 += __shfl_xor_sync(0xffffffffu, f0, 2);
        f1 += __shfl_xor_sync(0xffffffffu, f1, 1);
        f1 += __shfl_xor_sync(0xffffffffu, f1, 2);
        f2 += __shfl_xor_sync(0xffffffffu, f2, 1);
        f2 += __shfl_xor_sync(0xffffffffu, f2, 2);
        f3 += __shfl_xor_sync(0xffffffffu, f3, 1);
        f3 += __shfl_xor_sync(0xffffffffu, f3, 2);

        if (ksub == 0) {
            // ship peer-column sums immediately (release orders the v2 store)
            st_remote_v2(r_inbox + (unsigned)(p * 512), f2, f3);
            arrive_remote(r_mbar + (unsigned)(p * 8));

            // prefetch g_{t+1} while the flight is in the air
            const int tq = (t + 1 < T_STEPS) ? (t + 1) : (T_STEPS - 1);
            const float gn0 = gp0[tq * (B_SZ * N_HID)];
            const float gn1 = gp1[tq * (B_SZ * N_HID)];

            // late wait for peer sums
            if (p == 0) { mbar_wait_cluster(mb0, ph0); ph0 ^= 1; }
            else        { mbar_wait_cluster(mb0 + 8, ph1); ph1 ^= 1; }

            const float tot0 = f0 + inbox[p][2 * rl];
            const float tot1 = f1 + inbox[p][2 * rl + 1];

            xs0 = 0.9f * xs0 + 0.1f * tot0 + gr0;  gr0 = gn0;
            xs1 = 0.9f * xs1 + 0.1f * tot1 + gr1;  gr1 = gn1;

            r_s[nbuf][rl]      = ftanh(xs0);
            r_s[nbuf][rl + 64] = ftanh(xs1);
            sp0[t * (B_SZ * N_HID)] = xs0;         // fire-and-forget
            sp1[t * (B_SZ * N_HID)] = xs1;
        }

        __syncthreads();                 // r_s[nbuf] visible for t+1
    }

    CLUSTER_SYNC();                      // smem alive until peer traffic lands
}

// ---------------- Kernel B: z = tanh(states) @ Wout + bout ----------------
__global__ void __launch_bounds__(256, 1)
rnn_out_kernel(const float* __restrict__ states,  // [T*B, N]
               const float* __restrict__ Wout,    // [N, NOUT]
               const float* __restrict__ bout,    // [NOUT]
               float* __restrict__ outputs)       // [T*B, NOUT]
{
    __shared__ __align__(16) float srow[8][N_HID];

    const int tid  = threadIdx.x;
    const int wid  = tid >> 5;
    const int lane = tid & 31;
    const int o    = lane & 15;
    const int h    = lane >> 4;

    ull w[64];
#pragma unroll
    for (int j = 0; j < 64; ++j) {
        int nn = h * 128 + 2 * j;
        w[j] = pack2(Wout[nn * N_OUT + o], Wout[(nn + 1) * N_OUT + o]);
    }
    const float bo = bout[o];

    const int rows = T_STEPS * B_SZ;
    const int warps_total = (gridDim.x * blockDim.x) >> 5;
    int row = (blockIdx.x * blockDim.x + tid) >> 5;
    if (row >= rows) return;

    const float4* src = reinterpret_cast<const float4*>(states + (size_t)row * N_HID);
    float4 v0 = src[lane];
    float4 v1 = src[32 + lane];

    while (true) {
        const int nrow = row + warps_total;
        float4 n0, n1;
        if (nrow < rows) {
            const float4* nsrc = reinterpret_cast<const float4*>(states + (size_t)nrow * N_HID);
            n0 = nsrc[lane];
            n1 = nsrc[32 + lane];
        }

        v0.x = ftanh(v0.x); v0.y = ftanh(v0.y); v0.z = ftanh(v0.z); v0.w = ftanh(v0.w);
        v1.x = ftanh(v1.x); v1.y = ftanh(v1.y); v1.z = ftanh(v1.z); v1.w = ftanh(v1.w);
        float4* dst = reinterpret_cast<float4*>(&srow[wid][0]);
        dst[lane]      = v0;
        dst[32 + lane] = v1;
        __syncwarp();

        const ulonglong2* rp = reinterpret_cast<const ulonglong2*>(&srow[wid][h << 7]);
        ull a0 = 0, a1 = 0;
#pragma unroll
        for (int gq = 0; gq < 32; ++gq) {
            ulonglong2 q = rp[gq];
            ffma2(a0, w[2 * gq + 0], q.x);
            ffma2(a1, w[2 * gq + 1], q.y);
        }
        float zz = hadd2(a0) + hadd2(a1);
        zz += __shfl_xor_sync(0xffffffffu, zz, 16);
        if (h == 0)
            outputs[(size_t)row * N_OUT + o] = zz + bo;
        __syncwarp();

        if (nrow >= rows) break;
        row = nrow; v0 = n0; v1 = n1;
    }
}

extern "C" void kernel_launch(void* const* d_in, const int* in_sizes, int n_in,
                              void* d_out, int out_size) {
    const float* inputs = (const float*)d_in[0];
    const float* noise  = (const float*)d_in[1];
    const float* x0     = (const float*)d_in[2];
    const float* Win    = (const float*)d_in[3];
    const float* Wrec   = (const float*)d_in[4];
    const float* brec   = (const float*)d_in[5];
    const float* Wout   = (const float*)d_in[6];
    const float* bout   = (const float*)d_in[7];

    float* outputs = (float*)d_out;                                  // [T,B,NOUT]
    float* states  = (float*)d_out + (size_t)T_STEPS * B_SZ * N_OUT; // [T,B,N]

    uproj_kernel<<<dim3(T_STEPS * B_SZ / 8), dim3(256)>>>(inputs, noise, Win, brec);
    rnn_step_kernel<<<dim3(B_SZ * 2), dim3(256)>>>(x0, Wrec, states);
    rnn_out_kernel<<<dim3(592), dim3(256)>>>(states, Wout, bout, outputs);
}

// round 14
// speedup vs baseline: 1.2011x; 1.2011x over previous
#include <cuda_runtime.h>
#include <cstdint>

// Leaky RNN: x_t = 0.9*x_{t-1} + 0.1*(u@Win + tanh(x_{t-1})@Wrec + brec) + q_t
//            z_t = tanh(x_t)@Wout + bout
// T=1024, B=64, NIN=32, N=256, NOUT=16.
//
// Pre : g[t,b,n] = noise + 0.1*(u@Win + brec)
// A   : 64 CTAs = 32 batch-PAIRS x 2 cluster ranks (k-split halves).
//       Each CTA runs TWO batches, pipelined: batch1's dot hides batch0's
//       DSMEM flight, batch0's update hides batch1's. Weights shared across
//       batches (register-stationary, 64 ull). Exchange per batch = R9-proven
//       release-arrive/acquire-wait mbarrier protocol (128 arrives, cnt=128).
// B   : outputs = tanh(states) @ Wout + bout.

#define T_STEPS 1024
#define B_SZ    64
#define N_IN    32
#define N_HID   256
#define N_OUT   16

typedef unsigned long long ull;

__device__ float g_buf[T_STEPS * B_SZ * N_HID];

__device__ __forceinline__ void ffma2(ull& acc, ull a, ull b) {
    asm("fma.rn.f32x2 %0, %1, %2, %0;" : "+l"(acc) : "l"(a), "l"(b));
}
__device__ __forceinline__ ull pack2(float lo, float hi) {
    ull r; asm("mov.b64 %0, {%1, %2};" : "=l"(r) : "f"(lo), "f"(hi)); return r;
}
__device__ __forceinline__ float hadd2(ull a) {
    float lo, hi; asm("mov.b64 {%0, %1}, %2;" : "=f"(lo), "=f"(hi) : "l"(a));
    return lo + hi;
}
__device__ __forceinline__ float ftanh(float x) {
    float e = __expf(2.0f * x);
    return 1.0f - __fdividef(2.0f, e + 1.0f);
}
__device__ __forceinline__ unsigned mapa32(unsigned laddr, unsigned peer) {
    unsigned r;
    asm volatile("mapa.shared::cluster.u32 %0, %1, %2;" : "=r"(r) : "r"(laddr), "r"(peer));
    return r;
}
__device__ __forceinline__ void st_remote_f32(unsigned addr, float v) {
    asm volatile("st.shared::cluster.f32 [%0], %1;" :: "r"(addr), "f"(v) : "memory");
}
__device__ __forceinline__ void arrive_remote(unsigned addr) {
    asm volatile("mbarrier.arrive.release.cluster.shared::cluster.b64 _, [%0];"
                 :: "r"(addr) : "memory");
}
__device__ __forceinline__ void mbar_wait_cluster(unsigned addr, unsigned parity) {
    unsigned done;
    do {
        asm volatile(
            "{\n\t.reg .pred P;\n\t"
            "mbarrier.try_wait.parity.acquire.cluster.shared::cta.b64 P, [%1], %2, 0x989680;\n\t"
            "selp.b32 %0, 1, 0, P;\n\t}"
            : "=r"(done) : "r"(addr), "r"(parity) : "memory");
    } while (!done);
}
#define CLUSTER_SYNC() do { \
    asm volatile("barrier.cluster.arrive.aligned;" ::: "memory"); \
    asm volatile("barrier.cluster.wait.aligned;"   ::: "memory"); } while (0)

// ---------------- Pre-kernel: g = noise + 0.1*(u@Win + brec) ----------------
__global__ void __launch_bounds__(256)
uproj_kernel(const float* __restrict__ inputs,   // [T*B, NIN]
             const float* __restrict__ noise,    // [T*B, N]
             const float* __restrict__ Win,      // [NIN, N]
             const float* __restrict__ brec)     // [N]
{
    __shared__ float su[8][N_IN];
    const int tid = threadIdx.x;

    float w_in[N_IN];
#pragma unroll
    for (int i = 0; i < N_IN; ++i) w_in[i] = Win[i * N_HID + tid];
    const float br = brec[tid];

    const int row0 = blockIdx.x * 8;
    su[tid >> 5][tid & 31] = inputs[row0 * N_IN + tid];
    __syncthreads();

#pragma unroll
    for (int rr = 0; rr < 8; ++rr) {
        const int row = row0 + rr;
        float acc = br;
#pragma unroll
        for (int i = 0; i < N_IN; ++i) acc = fmaf(su[rr][i], w_in[i], acc);
        g_buf[row * N_HID + tid] = noise[row * N_HID + tid] + 0.1f * acc;
    }
}

// ---------------- Kernel A: recurrence, 2-batch pipelined ----------------
#define RP 136

__global__ void __launch_bounds__(256, 1) __cluster_dims__(2, 1, 1)
rnn_step_kernel(const float* __restrict__ x0,     // [B,N]
                const float* __restrict__ Wrec,   // [N,N]
                float* __restrict__ states)       // [T,B,N]
{
    __shared__ __align__(16) float r_s0[2][128], r_s1[2][128];
    __shared__ __align__(16) float sRed0[4][RP], sPeer0[4][RP];
    __shared__ __align__(16) float sRed1[4][RP], sPeer1[4][RP];
    __shared__ __align__(16) float inbox[2][2][128];   // [batch][parity][li]
    __shared__ __align__(8)  ull   mbar[4];            // [2*batch + parity]

    const int tid = threadIdx.x;
    const int pair = blockIdx.x >> 1;
    const unsigned rho = blockIdx.x & 1u;
    const int b0  = 2 * pair;            // batch pair
    const int s   = tid >> 6;            // k sub-slice 0..3
    const int c   = tid & 63;
    const int k0  = (int)rho * 128 + 32 * s;
    const int ownBase = (int)rho * 128;

    // shared weights: 4 cols {c,c+64,c+128,c+192} over own 32-k sub-slice
    ull W0[16], W1[16], W2[16], W3[16];
#pragma unroll
    for (int i = 0; i < 16; ++i) {
        const int k = k0 + 2 * i;
        W0[i] = pack2(Wrec[k * N_HID + c],       Wrec[(k + 1) * N_HID + c]);
        W1[i] = pack2(Wrec[k * N_HID + c + 64],  Wrec[(k + 1) * N_HID + c + 64]);
        W2[i] = pack2(Wrec[k * N_HID + c + 128], Wrec[(k + 1) * N_HID + c + 128]);
        W3[i] = pack2(Wrec[k * N_HID + c + 192], Wrec[(k + 1) * N_HID + c + 192]);
    }

    if (tid < 4) {
        asm volatile("mbarrier.init.shared.b64 [%0], %1;"
                     :: "r"((unsigned)__cvta_generic_to_shared(&mbar[tid])), "r"(128) : "memory");
    }

    float xa = 0.0f, xb = 0.0f, ga = 0.0f, gb = 0.0f;
    unsigned r_inbox = 0, r_mbar = 0;
    const float* gp = g_buf + b0 * N_HID + ownBase + tid;   // owner col (tid<128)
    float* sp = states + b0 * N_HID + ownBase + tid;        // batch b0; b1 = +N_HID

    if (tid < 128) {
        xa = x0[b0 * N_HID + ownBase + tid];
        xb = x0[(b0 + 1) * N_HID + ownBase + tid];
        r_s0[0][tid] = ftanh(xa);
        r_s1[0][tid] = ftanh(xb);
        ga = gp[0];
        gb = gp[N_HID];
    } else {
        const int li = tid - 128;
        r_inbox = mapa32((unsigned)__cvta_generic_to_shared(&inbox[0][0][li]), rho ^ 1u);
        r_mbar  = mapa32((unsigned)__cvta_generic_to_shared(&mbar[0]), rho ^ 1u);
    }

    __syncthreads();
    CLUSTER_SYNC();                       // peer mbar init visible

    const unsigned mbL = (unsigned)__cvta_generic_to_shared(&mbar[0]);
    int ph00 = 0, ph01 = 0, ph10 = 0, ph11 = 0;

#pragma unroll 1
    for (int t = 0; t < T_STEPS; ++t) {
        const int p    = t & 1;
        const int nbuf = p ^ 1;

        // ================= batch 0 dot =================
        {
            const ulonglong2* rp = reinterpret_cast<const ulonglong2*>(&r_s0[p][32 * s]);
            ull a0 = 0, a1 = 0, a2 = 0, a3 = 0;
#pragma unroll
            for (int q = 0; q < 8; ++q) {
                ulonglong2 v = rp[q];
                ffma2(a0, W0[2 * q], v.x);  ffma2(a0, W0[2 * q + 1], v.y);
                ffma2(a1, W1[2 * q], v.x);  ffma2(a1, W1[2 * q + 1], v.y);
                ffma2(a2, W2[2 * q], v.x);  ffma2(a2, W2[2 * q + 1], v.y);
                ffma2(a3, W3[2 * q], v.x);  ffma2(a3, W3[2 * q + 1], v.y);
            }
            const float p0 = hadd2(a0), p1 = hadd2(a1), p2 = hadd2(a2), p3 = hadd2(a3);
            if (rho == 0) {
                sRed0[s][c]  = p0;  sRed0[s][c + 64]  = p1;
                sPeer0[s][c] = p2;  sPeer0[s][c + 64] = p3;
            } else {
                sRed0[s][c]  = p2;  sRed0[s][c + 64]  = p3;
                sPeer0[s][c] = p0;  sPeer0[s][c + 64] = p1;
            }
        }
        __syncthreads();   // S1: b0 partials visible

        // senders: ship b0 sums NOW (flight overlaps b1 dot)
        if (tid >= 128) {
            const int li = tid - 128;
            const float ps = (sPeer0[0][li] + sPeer0[1][li])
                           + (sPeer0[2][li] + sPeer0[3][li]);
            st_remote_f32(r_inbox + (unsigned)(p * 512), ps);
            arrive_remote(r_mbar + (unsigned)(p * 8));
        }

        // ================= batch 1 dot (covers b0 flight) =================
        {
            const ulonglong2* rp = reinterpret_cast<const ulonglong2*>(&r_s1[p][32 * s]);
            ull a0 = 0, a1 = 0, a2 = 0, a3 = 0;
#pragma unroll
            for (int q = 0; q < 8; ++q) {
                ulonglong2 v = rp[q];
                ffma2(a0, W0[2 * q], v.x);  ffma2(a0, W0[2 * q + 1], v.y);
                ffma2(a1, W1[2 * q], v.x);  ffma2(a1, W1[2 * q + 1], v.y);
                ffma2(a2, W2[2 * q], v.x);  ffma2(a2, W2[2 * q + 1], v.y);
                ffma2(a3, W3[2 * q], v.x);  ffma2(a3, W3[2 * q + 1], v.y);
            }
            const float p0 = hadd2(a0), p1 = hadd2(a1), p2 = hadd2(a2), p3 = hadd2(a3);
            if (rho == 0) {
                sRed1[s][c]  = p0;  sRed1[s][c + 64]  = p1;
                sPeer1[s][c] = p2;  sPeer1[s][c + 64] = p3;
            } else {
                sRed1[s][c]  = p2;  sRed1[s][c + 64]  = p3;
                sPeer1[s][c] = p0;  sPeer1[s][c + 64] = p1;
            }
        }
        __syncthreads();   // S2: b1 partials visible

        if (tid >= 128) {
            // ship b1 sums (flight overlaps owner b0 update)
            const int li = tid - 128;
            const float ps = (sPeer1[0][li] + sPeer1[1][li])
                           + (sPeer1[2][li] + sPeer1[3][li]);
            st_remote_f32(r_inbox + (unsigned)(1024 + p * 512), ps);
            arrive_remote(r_mbar + (unsigned)(16 + p * 8));
        } else {
            const int tq = (t + 1 < T_STEPS) ? (t + 1) : (T_STEPS - 1);
            const float gna = gp[tq * (B_SZ * N_HID)];
            const float gnb = gp[tq * (B_SZ * N_HID) + N_HID];

            // ---- batch 0: reduce, wait (flight had b1-dot time), update ----
            const float own0 = (sRed0[0][tid] + sRed0[1][tid])
                             + (sRed0[2][tid] + sRed0[3][tid]);
            if (p == 0) { mbar_wait_cluster(mbL, ph00); ph00 ^= 1; }
            else        { mbar_wait_cluster(mbL + 8, ph01); ph01 ^= 1; }
            xa = 0.9f * xa + 0.1f * (own0 + inbox[0][p][tid]) + ga;
            ga = gna;
            r_s0[nbuf][tid] = ftanh(xa);
            sp[t * (B_SZ * N_HID)] = xa;

            // ---- batch 1: reduce, wait, update ----
            const float own1 = (sRed1[0][tid] + sRed1[1][tid])
                             + (sRed1[2][tid] + sRed1[3][tid]);
            if (p == 0) { mbar_wait_cluster(mbL + 16, ph10); ph10 ^= 1; }
            else        { mbar_wait_cluster(mbL + 24, ph11); ph11 ^= 1; }
            xb = 0.9f * xb + 0.1f * (own1 + inbox[1][p][tid]) + gb;
            gb = gnb;
            r_s1[nbuf][tid] = ftanh(xb);
            sp[t * (B_SZ * N_HID) + N_HID] = xb;
        }

        __syncthreads();   // S3: r_s*[nbuf] ready; sRed/sPeer reusable
    }

    CLUSTER_SYNC();        // smem alive until last peer traffic lands
}

// ---------------- Kernel B: z = tanh(states) @ Wout + bout ----------------
__global__ void __launch_bounds__(256, 1)
rnn_out_kernel(const float* __restrict__ states,  // [T*B, N]
               const float* __restrict__ Wout,    // [N, NOUT]
               const float* __restrict__ bout,    // [NOUT]
               float* __restrict__ outputs)       // [T*B, NOUT]
{
    __shared__ __align__(16) float srow[8][N_HID];

    const int tid  = threadIdx.x;
    const int wid  = tid >> 5;
    const int lane = tid & 31;
    const int o    = lane & 15;
    const int h    = lane >> 4;

    ull w[64];
#pragma unroll
    for (int j = 0; j < 64; ++j) {
        int nn = h * 128 + 2 * j;
        w[j] = pack2(Wout[nn * N_OUT + o], Wout[(nn + 1) * N_OUT + o]);
    }
    const float bo = bout[o];

    const int rows = T_STEPS * B_SZ;
    const int warps_total = (gridDim.x * blockDim.x) >> 5;
    int row = (blockIdx.x * blockDim.x + tid) >> 5;
    if (row >= rows) return;

    const float4* src = reinterpret_cast<const float4*>(states + (size_t)row * N_HID);
    float4 v0 = src[lane];
    float4 v1 = src[32 + lane];

    while (true) {
        const int nrow = row + warps_total;
        float4 n0, n1;
        if (nrow < rows) {
            const float4* nsrc = reinterpret_cast<const float4*>(states + (size_t)nrow * N_HID);
            n0 = nsrc[lane];
            n1 = nsrc[32 + lane];
        }

        v0.x = ftanh(v0.x); v0.y = ftanh(v0.y); v0.z = ftanh(v0.z); v0.w = ftanh(v0.w);
        v1.x = ftanh(v1.x); v1.y = ftanh(v1.y); v1.z = ftanh(v1.z); v1.w = ftanh(v1.w);
        float4* dst = reinterpret_cast<float4*>(&srow[wid][0]);
        dst[lane]      = v0;
        dst[32 + lane] = v1;
        __syncwarp();

        const ulonglong2* rp = reinterpret_cast<const ulonglong2*>(&srow[wid][h << 7]);
        ull a0 = 0, a1 = 0;
#pragma unroll
        for (int gq = 0; gq < 32; ++gq) {
            ulonglong2 q = rp[gq];
            ffma2(a0, w[2 * gq + 0], q.x);
            ffma2(a1, w[2 * gq + 1], q.y);
        }
        float zz = hadd2(a0) + hadd2(a1);
        zz += __shfl_xor_sync(0xffffffffu, zz, 16);
        if (h == 0)
            outputs[(size_t)row * N_OUT + o] = zz + bo;
        __syncwarp();

        if (nrow >= rows) break;
        row = nrow; v0 = n0; v1 = n1;
    }
}

extern "C" void kernel_launch(void* const* d_in, const int* in_sizes, int n_in,
                              void* d_out, int out_size) {
    const float* inputs = (const float*)d_in[0];
    const float* noise  = (const float*)d_in[1];
    const float* x0     = (const float*)d_in[2];
    const float* Win    = (const float*)d_in[3];
    const float* Wrec   = (const float*)d_in[4];
    const float* brec   = (const float*)d_in[5];
    const float* Wout   = (const float*)d_in[6];
    const float* bout   = (const float*)d_in[7];

    float* outputs = (float*)d_out;                                  // [T,B,NOUT]
    float* states  = (float*)d_out + (size_t)T_STEPS * B_SZ * N_OUT; // [T,B,N]

    uproj_kernel<<<dim3(T_STEPS * B_SZ / 8), dim3(256)>>>(inputs, noise, Win, brec);
    rnn_step_kernel<<<dim3(B_SZ), dim3(256)>>>(x0, Wrec, states);
    rnn_out_kernel<<<dim3(592), dim3(256)>>>(states, Wout, bout, outputs);
}

// round 15
// speedup vs baseline: 1.2567x; 1.0463x over previous
#include <cuda_runtime.h>
#include <cstdint>

// Leaky RNN: x_t = 0.9*x_{t-1} + 0.1*(u@Win + tanh(x_{t-1})@Wrec + brec) + q_t
//            z_t = tanh(x_t)@Wout + bout
// T=1024, B=64, NIN=32, N=256, NOUT=16.
//
// Pre : g[t,b,n] = noise + 0.1*(u@Win + brec)
// A   : 128 CTAs = 64 batches x 2 cluster ranks (k-split halves), R9 protocol.
//       thread (w=tid>>5, l=tid&31): ksub=l>>3, cc=8w+(l&7).
//       2 own + 2 peer cols x 32 k, 64 ull weights in regs.
//       PEER dot first -> in-warp shfl reduce (xor 8,16) -> lanes l<8 send
//       final peer sums EARLY (release-arrive, 64 arrives) -> own dot + smem
//       reduce covers the DSMEM flight -> owner waits late (mostly free).
// B   : outputs = tanh(states) @ Wout + bout.

#define T_STEPS 1024
#define B_SZ    64
#define N_IN    32
#define N_HID   256
#define N_OUT   16

typedef unsigned long long ull;

__device__ float g_buf[T_STEPS * B_SZ * N_HID];

__device__ __forceinline__ void ffma2(ull& acc, ull a, ull b) {
    asm("fma.rn.f32x2 %0, %1, %2, %0;" : "+l"(acc) : "l"(a), "l"(b));
}
__device__ __forceinline__ ull pack2(float lo, float hi) {
    ull r; asm("mov.b64 %0, {%1, %2};" : "=l"(r) : "f"(lo), "f"(hi)); return r;
}
__device__ __forceinline__ float hadd2(ull a) {
    float lo, hi; asm("mov.b64 {%0, %1}, %2;" : "=f"(lo), "=f"(hi) : "l"(a));
    return lo + hi;
}
__device__ __forceinline__ float ftanh(float x) {
    float e = __expf(2.0f * x);
    return 1.0f - __fdividef(2.0f, e + 1.0f);
}
__device__ __forceinline__ unsigned mapa32(unsigned laddr, unsigned peer) {
    unsigned r;
    asm volatile("mapa.shared::cluster.u32 %0, %1, %2;" : "=r"(r) : "r"(laddr), "r"(peer));
    return r;
}
__device__ __forceinline__ void st_remote_f32(unsigned addr, float v) {
    asm volatile("st.shared::cluster.f32 [%0], %1;" :: "r"(addr), "f"(v) : "memory");
}
__device__ __forceinline__ void arrive_remote(unsigned addr) {
    asm volatile("mbarrier.arrive.release.cluster.shared::cluster.b64 _, [%0];"
                 :: "r"(addr) : "memory");
}
__device__ __forceinline__ void mbar_wait_cluster(unsigned addr, unsigned parity) {
    unsigned done;
    do {
        asm volatile(
            "{\n\t.reg .pred P;\n\t"
            "mbarrier.try_wait.parity.acquire.cluster.shared::cta.b64 P, [%1], %2, 0x989680;\n\t"
            "selp.b32 %0, 1, 0, P;\n\t}"
            : "=r"(done) : "r"(addr), "r"(parity) : "memory");
    } while (!done);
}
#define CLUSTER_SYNC() do { \
    asm volatile("barrier.cluster.arrive.aligned;" ::: "memory"); \
    asm volatile("barrier.cluster.wait.aligned;"   ::: "memory"); } while (0)

// ---------------- Pre-kernel: g = noise + 0.1*(u@Win + brec) ----------------
__global__ void __launch_bounds__(256)
uproj_kernel(const float* __restrict__ inputs,   // [T*B, NIN]
             const float* __restrict__ noise,    // [T*B, N]
             const float* __restrict__ Win,      // [NIN, N]
             const float* __restrict__ brec)     // [N]
{
    __shared__ float su[8][N_IN];
    const int tid = threadIdx.x;

    float w_in[N_IN];
#pragma unroll
    for (int i = 0; i < N_IN; ++i) w_in[i] = Win[i * N_HID + tid];
    const float br = brec[tid];

    const int row0 = blockIdx.x * 8;
    su[tid >> 5][tid & 31] = inputs[row0 * N_IN + tid];
    __syncthreads();

#pragma unroll
    for (int rr = 0; rr < 8; ++rr) {
        const int row = row0 + rr;
        float acc = br;
#pragma unroll
        for (int i = 0; i < N_IN; ++i) acc = fmaf(su[rr][i], w_in[i], acc);
        g_buf[row * N_HID + tid] = noise[row * N_HID + tid] + 0.1f * acc;
    }
}

// ---------------- Kernel A: recurrence (early shuffle-reduced peer send) ----------------
#define RP 136

__global__ void __launch_bounds__(256, 1) __cluster_dims__(2, 1, 1)
rnn_step_kernel(const float* __restrict__ x0,     // [B,N]
                const float* __restrict__ Wrec,   // [N,N]
                float* __restrict__ states)       // [T,B,N]
{
    __shared__ __align__(16) float r_s[2][128];    // own-half r, dbl-buffered
    __shared__ __align__(16) float sRed[4][RP];    // own-col partials [ksub][li]
    __shared__ __align__(16) float inbox[2][128];  // peer sums for my cols
    __shared__ __align__(8)  ull   mbar[2];

    const int tid = threadIdx.x;
    const int b   = blockIdx.x >> 1;
    const unsigned rho = blockIdx.x & 1u;
    const int w    = tid >> 5;
    const int l    = tid & 31;
    const int ksub = l >> 3;             // k sub-slice 0..3 (32 k each)
    const int cc   = 8 * w + (l & 7);    // column base 0..63

    const int ownBase  = (int)rho * 128;
    const int peerBase = ((int)rho ^ 1) * 128;
    const int k0 = ownBase + 32 * ksub;  // own k-half, sub-slice

    // weights: 2 own + 2 peer columns over own 32-k sub-slice = 64 ull
    ull WO0[16], WO1[16], WP0[16], WP1[16];
#pragma unroll
    for (int i = 0; i < 16; ++i) {
        const int k = k0 + 2 * i;
        WO0[i] = pack2(Wrec[k * N_HID + ownBase + cc],
                       Wrec[(k + 1) * N_HID + ownBase + cc]);
        WO1[i] = pack2(Wrec[k * N_HID + ownBase + cc + 64],
                       Wrec[(k + 1) * N_HID + ownBase + cc + 64]);
        WP0[i] = pack2(Wrec[k * N_HID + peerBase + cc],
                       Wrec[(k + 1) * N_HID + peerBase + cc]);
        WP1[i] = pack2(Wrec[k * N_HID + peerBase + cc + 64],
                       Wrec[(k + 1) * N_HID + peerBase + cc + 64]);
    }

    if (tid < 2) {
        asm volatile("mbarrier.init.shared.b64 [%0], %1;"
                     :: "r"((unsigned)__cvta_generic_to_shared(&mbar[tid])), "r"(64) : "memory");
    }

    // remote targets: peer inbox[0][cc] (+256B for cc+64), peer mbar
    const unsigned r_inbox = mapa32(
        (unsigned)__cvta_generic_to_shared(&inbox[0][cc]), rho ^ 1u);
    const unsigned r_mbar = mapa32(
        (unsigned)__cvta_generic_to_shared(&mbar[0]), rho ^ 1u);

    float x = 0.0f, greg = 0.0f;
    const float* gp = g_buf + b * N_HID + ownBase + tid;   // owner col (tid<128)
    float* sp = states + b * N_HID + ownBase + tid;

    if (tid < 128) {
        x = x0[b * N_HID + ownBase + tid];
        r_s[0][tid] = ftanh(x);
        greg = gp[0];
    }

    __syncthreads();
    CLUSTER_SYNC();                      // peer mbar init visible

    const unsigned mb0 = (unsigned)__cvta_generic_to_shared(&mbar[0]);
    int ph0 = 0, ph1 = 0;

#pragma unroll 1
    for (int t = 0; t < T_STEPS; ++t) {
        const int p    = t & 1;
        const int nbuf = p ^ 1;

        // ---- load own 32-float r sub-slice (broadcast within 8-lane groups) ----
        const ulonglong2* rp = reinterpret_cast<const ulonglong2*>(&r_s[p][32 * ksub]);
        ulonglong2 rv[8];
#pragma unroll
        for (int q = 0; q < 8; ++q) rv[q] = rp[q];

        // ---- PEER columns first: 32 FFMA2 ----
        ull pb0 = 0, pb1 = 0;
#pragma unroll
        for (int q = 0; q < 8; ++q) {
            ffma2(pb0, WP0[2 * q], rv[q].x);  ffma2(pb0, WP0[2 * q + 1], rv[q].y);
            ffma2(pb1, WP1[2 * q], rv[q].x);  ffma2(pb1, WP1[2 * q + 1], rv[q].y);
        }
        float f2 = hadd2(pb0), f3 = hadd2(pb1);
        // in-warp ksub reduce: lanes {l, l^8, l^16, l^24} share the same cc
        f2 += __shfl_xor_sync(0xffffffffu, f2, 8);
        f3 += __shfl_xor_sync(0xffffffffu, f3, 8);
        f2 += __shfl_xor_sync(0xffffffffu, f2, 16);
        f3 += __shfl_xor_sync(0xffffffffu, f3, 16);

        // lanes l<8: ship final peer sums EARLY (release orders both stores)
        if (l < 8) {
            const unsigned dst = r_inbox + (unsigned)(p * 512);
            st_remote_f32(dst,       f2);
            st_remote_f32(dst + 256, f3);           // col cc+64 = +64 floats
            arrive_remote(r_mbar + (unsigned)(p * 8));
        }

        // ---- OWN columns: 32 FFMA2 (covers the flight) ----
        ull pa0 = 0, pa1 = 0;
#pragma unroll
        for (int q = 0; q < 8; ++q) {
            ffma2(pa0, WO0[2 * q], rv[q].x);  ffma2(pa0, WO0[2 * q + 1], rv[q].y);
            ffma2(pa1, WO1[2 * q], rv[q].x);  ffma2(pa1, WO1[2 * q + 1], rv[q].y);
        }
        sRed[ksub][cc]      = hadd2(pa0);
        sRed[ksub][cc + 64] = hadd2(pa1);

        __syncthreads();                 // S1: own partials visible

        if (tid < 128) {
            const int tq = (t + 1 < T_STEPS) ? (t + 1) : (T_STEPS - 1);
            const float gnext = gp[tq * (B_SZ * N_HID)];

            const float own = (sRed[0][tid] + sRed[1][tid])
                            + (sRed[2][tid] + sRed[3][tid]);

            if (p == 0) { mbar_wait_cluster(mb0, ph0); ph0 ^= 1; }
            else        { mbar_wait_cluster(mb0 + 8, ph1); ph1 ^= 1; }

            x = 0.9f * x + 0.1f * (own + inbox[p][tid]) + greg;
            greg = gnext;
            r_s[nbuf][tid] = ftanh(x);
            sp[t * (B_SZ * N_HID)] = x;  // fire-and-forget
        }

        __syncthreads();                 // S2: r_s[nbuf] ready; sRed reusable
    }

    CLUSTER_SYNC();                      // smem alive until peer traffic lands
}

// ---------------- Kernel B: z = tanh(states) @ Wout + bout ----------------
__global__ void __launch_bounds__(256, 1)
rnn_out_kernel(const float* __restrict__ states,  // [T*B, N]
               const float* __restrict__ Wout,    // [N, NOUT]
               const float* __restrict__ bout,    // [NOUT]
               float* __restrict__ outputs)       // [T*B, NOUT]
{
    __shared__ __align__(16) float srow[8][N_HID];

    const int tid  = threadIdx.x;
    const int wid  = tid >> 5;
    const int lane = tid & 31;
    const int o    = lane & 15;
    const int h    = lane >> 4;

    ull w[64];
#pragma unroll
    for (int j = 0; j < 64; ++j) {
        int nn = h * 128 + 2 * j;
        w[j] = pack2(Wout[nn * N_OUT + o], Wout[(nn + 1) * N_OUT + o]);
    }
    const float bo = bout[o];

    const int rows = T_STEPS * B_SZ;
    const int warps_total = (gridDim.x * blockDim.x) >> 5;
    int row = (blockIdx.x * blockDim.x + tid) >> 5;
    if (row >= rows) return;

    const float4* src = reinterpret_cast<const float4*>(states + (size_t)row * N_HID);
    float4 v0 = src[lane];
    float4 v1 = src[32 + lane];

    while (true) {
        const int nrow = row + warps_total;
        float4 n0, n1;
        if (nrow < rows) {
            const float4* nsrc = reinterpret_cast<const float4*>(states + (size_t)nrow * N_HID);
            n0 = nsrc[lane];
            n1 = nsrc[32 + lane];
        }

        v0.x = ftanh(v0.x); v0.y = ftanh(v0.y); v0.z = ftanh(v0.z); v0.w = ftanh(v0.w);
        v1.x = ftanh(v1.x); v1.y = ftanh(v1.y); v1.z = ftanh(v1.z); v1.w = ftanh(v1.w);
        float4* dst = reinterpret_cast<float4*>(&srow[wid][0]);
        dst[lane]      = v0;
        dst[32 + lane] = v1;
        __syncwarp();

        const ulonglong2* rp = reinterpret_cast<const ulonglong2*>(&srow[wid][h << 7]);
        ull a0 = 0, a1 = 0;
#pragma unroll
        for (int gq = 0; gq < 32; ++gq) {
            ulonglong2 q = rp[gq];
            ffma2(a0, w[2 * gq + 0], q.x);
            ffma2(a1, w[2 * gq + 1], q.y);
        }
        float zz = hadd2(a0) + hadd2(a1);
        zz += __shfl_xor_sync(0xffffffffu, zz, 16);
        if (h == 0)
            outputs[(size_t)row * N_OUT + o] = zz + bo;
        __syncwarp();

        if (nrow >= rows) break;
        row = nrow; v0 = n0; v1 = n1;
    }
}

extern "C" void kernel_launch(void* const* d_in, const int* in_sizes, int n_in,
                              void* d_out, int out_size) {
    const float* inputs = (const float*)d_in[0];
    const float* noise  = (const float*)d_in[1];
    const float* x0     = (const float*)d_in[2];
    const float* Win    = (const float*)d_in[3];
    const float* Wrec   = (const float*)d_in[4];
    const float* brec   = (const float*)d_in[5];
    const float* Wout   = (const float*)d_in[6];
    const float* bout   = (const float*)d_in[7];

    float* outputs = (float*)d_out;                                  // [T,B,NOUT]
    float* states  = (float*)d_out + (size_t)T_STEPS * B_SZ * N_OUT; // [T,B,N]

    uproj_kernel<<<dim3(T_STEPS * B_SZ / 8), dim3(256)>>>(inputs, noise, Win, brec);
    rnn_step_kernel<<<dim3(B_SZ * 2), dim3(256)>>>(x0, Wrec, states);
    rnn_out_kernel<<<dim3(592), dim3(256)>>>(states, Wout, bout, outputs);
}

// round 16
// speedup vs baseline: 1.8507x; 1.4727x over previous
#include <cuda_runtime.h>
#include <cstdint>

// Leaky RNN: x_t = 0.9*x_{t-1} + 0.1*(u@Win + tanh(x_{t-1})@Wrec + brec) + q_t
//            z_t = tanh(x_t)@Wout + bout
// T=1024, B=64, NIN=32, N=256, NOUT=16.
//
// R9 kernel (best: 891us) with ONE change: the consumer mbarrier wait uses
// acquire.cta (canonical Blackwell consumer wait) instead of acquire.cluster.
// Producer side unchanged: st.shared::cluster + mbarrier.arrive.release.cluster.
//
// Pre : g[t,b,n] = noise + 0.1*(u@Win + brec)
// A   : 128 CTAs = 64 batches x 2 cluster ranks (k-split halves).
//       thread (s=tid>>6, c=tid&63) computes 4 cols {c+64j} over own 32-k sub.
//       64 ull weights in regs. Partials via smem; peer-col sums cross via
//       st.shared::cluster + arrive.release; owner waits (acquire.cta) late.
// B   : outputs = tanh(states) @ Wout + bout.

#define T_STEPS 1024
#define B_SZ    64
#define N_IN    32
#define N_HID   256
#define N_OUT   16

typedef unsigned long long ull;

__device__ float g_buf[T_STEPS * B_SZ * N_HID];

__device__ __forceinline__ void ffma2(ull& acc, ull a, ull b) {
    asm("fma.rn.f32x2 %0, %1, %2, %0;" : "+l"(acc) : "l"(a), "l"(b));
}
__device__ __forceinline__ ull pack2(float lo, float hi) {
    ull r; asm("mov.b64 %0, {%1, %2};" : "=l"(r) : "f"(lo), "f"(hi)); return r;
}
__device__ __forceinline__ float hadd2(ull a) {
    float lo, hi; asm("mov.b64 {%0, %1}, %2;" : "=f"(lo), "=f"(hi) : "l"(a));
    return lo + hi;
}
__device__ __forceinline__ float ftanh(float x) {
    float e = __expf(2.0f * x);
    return 1.0f - __fdividef(2.0f, e + 1.0f);
}
__device__ __forceinline__ unsigned mapa32(unsigned laddr, unsigned peer) {
    unsigned r;
    asm volatile("mapa.shared::cluster.u32 %0, %1, %2;" : "=r"(r) : "r"(laddr), "r"(peer));
    return r;
}
__device__ __forceinline__ void st_remote_f32(unsigned addr, float v) {
    asm volatile("st.shared::cluster.f32 [%0], %1;" :: "r"(addr), "f"(v) : "memory");
}
__device__ __forceinline__ void arrive_remote(unsigned addr) {
    asm volatile("mbarrier.arrive.release.cluster.shared::cluster.b64 _, [%0];"
                 :: "r"(addr) : "memory");
}
// Canonical consumer wait: acquire at CTA scope (barrier + data are in local smem).
__device__ __forceinline__ void mbar_wait_cta(unsigned addr, unsigned parity) {
    unsigned done;
    do {
        asm volatile(
            "{\n\t.reg .pred P;\n\t"
            "mbarrier.try_wait.parity.acquire.cta.shared::cta.b64 P, [%1], %2, 0x989680;\n\t"
            "selp.b32 %0, 1, 0, P;\n\t}"
            : "=r"(done) : "r"(addr), "r"(parity) : "memory");
    } while (!done);
}
#define CLUSTER_SYNC() do { \
    asm volatile("barrier.cluster.arrive.aligned;" ::: "memory"); \
    asm volatile("barrier.cluster.wait.aligned;"   ::: "memory"); } while (0)

// ---------------- Pre-kernel: g = noise + 0.1*(u@Win + brec) ----------------
__global__ void __launch_bounds__(256)
uproj_kernel(const float* __restrict__ inputs,   // [T*B, NIN]
             const float* __restrict__ noise,    // [T*B, N]
             const float* __restrict__ Win,      // [NIN, N]
             const float* __restrict__ brec)     // [N]
{
    __shared__ float su[8][N_IN];
    const int tid = threadIdx.x;

    float w_in[N_IN];
#pragma unroll
    for (int i = 0; i < N_IN; ++i) w_in[i] = Win[i * N_HID + tid];
    const float br = brec[tid];

    const int row0 = blockIdx.x * 8;
    su[tid >> 5][tid & 31] = inputs[row0 * N_IN + tid];
    __syncthreads();

#pragma unroll
    for (int rr = 0; rr < 8; ++rr) {
        const int row = row0 + rr;
        float acc = br;
#pragma unroll
        for (int i = 0; i < N_IN; ++i) acc = fmaf(su[rr][i], w_in[i], acc);
        g_buf[row * N_HID + tid] = noise[row * N_HID + tid] + 0.1f * acc;
    }
}

// ---------------- Kernel A: recurrence (R9, cta-scope wait) ----------------
#define RP 136     // padded partial row (conflict-free, 16B-mult)

__global__ void __launch_bounds__(256, 1) __cluster_dims__(2, 1, 1)
rnn_step_kernel(const float* __restrict__ x0,     // [B,N]
                const float* __restrict__ Wrec,   // [N,N]
                float* __restrict__ states)       // [T,B,N]
{
    __shared__ __align__(16) float r_s[2][128];    // own-half r, dbl-buffered
    __shared__ __align__(16) float sRed[4][RP];    // own-col partials  [s][local col]
    __shared__ __align__(16) float sPeer[4][RP];   // peer-col partials [s][peer-local col]
    __shared__ __align__(16) float inbox[2][128];  // peer's summed partials for my cols
    __shared__ __align__(8)  ull   mbar[2];

    const int tid = threadIdx.x;
    const int b   = blockIdx.x >> 1;
    const unsigned rho = blockIdx.x & 1u;
    const int s   = tid >> 6;            // k sub-slice 0..3
    const int c   = tid & 63;            // column base within group
    const int k0  = (int)rho * 128 + 32 * s;

    // weights: Wj[i] = (Wrec[k0+2i][c+64j], Wrec[k0+2i+1][c+64j]), 64 ull total
    ull W0[16], W1[16], W2[16], W3[16];
#pragma unroll
    for (int i = 0; i < 16; ++i) {
        const int k = k0 + 2 * i;
        W0[i] = pack2(Wrec[k * N_HID + c],       Wrec[(k + 1) * N_HID + c]);
        W1[i] = pack2(Wrec[k * N_HID + c + 64],  Wrec[(k + 1) * N_HID + c + 64]);
        W2[i] = pack2(Wrec[k * N_HID + c + 128], Wrec[(k + 1) * N_HID + c + 128]);
        W3[i] = pack2(Wrec[k * N_HID + c + 192], Wrec[(k + 1) * N_HID + c + 192]);
    }

    if (tid == 0) {
        asm volatile("mbarrier.init.shared.b64 [%0], %1;"
                     :: "r"((unsigned)__cvta_generic_to_shared(&mbar[0])), "r"(128) : "memory");
        asm volatile("mbarrier.init.shared.b64 [%0], %1;"
                     :: "r"((unsigned)__cvta_generic_to_shared(&mbar[1])), "r"(128) : "memory");
    }

    float x = 0.0f, greg = 0.0f;
    unsigned r_inbox = 0, r_mbar = 0;
    const float* gp = g_buf + b * N_HID + (int)rho * 128 + tid;   // owner cols (tid<128)
    float* sp = states + b * N_HID + (int)rho * 128 + tid;

    if (tid < 128) {                      // state owner for local col tid
        x = x0[b * N_HID + (int)rho * 128 + tid];
        r_s[0][tid] = ftanh(x);
        greg = gp[0];
    } else {                              // sender for peer-local col tid-128
        const int li = tid - 128;
        unsigned l_in = (unsigned)__cvta_generic_to_shared(&inbox[0][li]);
        r_inbox = mapa32(l_in, rho ^ 1u);
        unsigned l_mb = (unsigned)__cvta_generic_to_shared(&mbar[0]);
        r_mbar = mapa32(l_mb, rho ^ 1u);
    }

    __syncthreads();
    CLUSTER_SYNC();                       // peer mbar init visible

    const unsigned mb0 = (unsigned)__cvta_generic_to_shared(&mbar[0]);
    int ph0 = 0, ph1 = 0;

#pragma unroll 1
    for (int t = 0; t < T_STEPS; ++t) {
        const int p  = t & 1;
        const int nbuf = p ^ 1;

        // ---- dot: 32-float r sub-slice, 8 LDS.128, 64 FFMA2 ----
        const ulonglong2* rp = reinterpret_cast<const ulonglong2*>(&r_s[p][32 * s]);
        ull a0 = 0, a1 = 0, a2 = 0, a3 = 0;
#pragma unroll
        for (int q = 0; q < 8; ++q) {
            ulonglong2 v = rp[q];
            ffma2(a0, W0[2 * q], v.x);  ffma2(a0, W0[2 * q + 1], v.y);
            ffma2(a1, W1[2 * q], v.x);  ffma2(a1, W1[2 * q + 1], v.y);
            ffma2(a2, W2[2 * q], v.x);  ffma2(a2, W2[2 * q + 1], v.y);
            ffma2(a3, W3[2 * q], v.x);  ffma2(a3, W3[2 * q + 1], v.y);
        }
        const float p0 = hadd2(a0), p1 = hadd2(a1), p2 = hadd2(a2), p3 = hadd2(a3);

        // own cols = [128rho,128rho+128) -> j-offset 2*rho; peer = other two
        if (rho == 0) {
            sRed[s][c]       = p0;  sRed[s][c + 64]  = p1;
            sPeer[s][c]      = p2;  sPeer[s][c + 64] = p3;
        } else {
            sRed[s][c]       = p2;  sRed[s][c + 64]  = p3;
            sPeer[s][c]      = p0;  sPeer[s][c + 64] = p1;
        }

        __syncthreads();    // partials visible

        if (tid < 128) {
            const int tq = (t + 1 < T_STEPS) ? (t + 1) : (T_STEPS - 1);
            const float gnext = gp[tq * (B_SZ * N_HID)];

            float own = (sRed[0][tid] + sRed[1][tid]) + (sRed[2][tid] + sRed[3][tid]);

            if (p == 0) { mbar_wait_cta(mb0, ph0); ph0 ^= 1; }
            else        { mbar_wait_cta(mb0 + 8, ph1); ph1 ^= 1; }

            const float tot = own + inbox[p][tid];
            x = 0.9f * x + 0.1f * tot + greg;
            greg = gnext;
            r_s[nbuf][tid] = ftanh(x);
            sp[t * (B_SZ * N_HID)] = x;
        } else {
            const int li = tid - 128;
            const float ps = (sPeer[0][li] + sPeer[1][li]) + (sPeer[2][li] + sPeer[3][li]);
            st_remote_f32(r_inbox + (unsigned)(p * 512), ps);
            arrive_remote(r_mbar + (unsigned)(p * 8));
        }

        __syncthreads();    // r_s[nbuf] ready; sRed/sPeer reusable
    }

    CLUSTER_SYNC();
}

// ---------------- Kernel B: z = tanh(states) @ Wout + bout ----------------
__global__ void __launch_bounds__(256, 1)
rnn_out_kernel(const float* __restrict__ states,  // [T*B, N]
               const float* __restrict__ Wout,    // [N, NOUT]
               const float* __restrict__ bout,    // [NOUT]
               float* __restrict__ outputs)       // [T*B, NOUT]
{
    __shared__ __align__(16) float srow[8][N_HID];

    const int tid  = threadIdx.x;
    const int wid  = tid >> 5;
    const int lane = tid & 31;
    const int o    = lane & 15;
    const int h    = lane >> 4;

    ull w[64];
#pragma unroll
    for (int j = 0; j < 64; ++j) {
        int nn = h * 128 + 2 * j;
        w[j] = pack2(Wout[nn * N_OUT + o], Wout[(nn + 1) * N_OUT + o]);
    }
    const float bo = bout[o];

    const int rows = T_STEPS * B_SZ;
    const int warps_total = (gridDim.x * blockDim.x) >> 5;
    int row = (blockIdx.x * blockDim.x + tid) >> 5;
    if (row >= rows) return;

    const float4* src = reinterpret_cast<const float4*>(states + (size_t)row * N_HID);
    float4 v0 = src[lane];
    float4 v1 = src[32 + lane];

    while (true) {
        const int nrow = row + warps_total;
        float4 n0, n1;
        if (nrow < rows) {
            const float4* nsrc = reinterpret_cast<const float4*>(states + (size_t)nrow * N_HID);
            n0 = nsrc[lane];
            n1 = nsrc[32 + lane];
        }

        v0.x = ftanh(v0.x); v0.y = ftanh(v0.y); v0.z = ftanh(v0.z); v0.w = ftanh(v0.w);
        v1.x = ftanh(v1.x); v1.y = ftanh(v1.y); v1.z = ftanh(v1.z); v1.w = ftanh(v1.w);
        float4* dst = reinterpret_cast<float4*>(&srow[wid][0]);
        dst[lane]      = v0;
        dst[32 + lane] = v1;
        __syncwarp();

        const ulonglong2* rp = reinterpret_cast<const ulonglong2*>(&srow[wid][h << 7]);
        ull a0 = 0, a1 = 0;
#pragma unroll
        for (int gq = 0; gq < 32; ++gq) {
            ulonglong2 q = rp[gq];
            ffma2(a0, w[2 * gq + 0], q.x);
            ffma2(a1, w[2 * gq + 1], q.y);
        }
        float zz = hadd2(a0) + hadd2(a1);
        zz += __shfl_xor_sync(0xffffffffu, zz, 16);
        if (h == 0)
            outputs[(size_t)row * N_OUT + o] = zz + bo;
        __syncwarp();

        if (nrow >= rows) break;
        row = nrow; v0 = n0; v1 = n1;
    }
}

extern "C" void kernel_launch(void* const* d_in, const int* in_sizes, int n_in,
                              void* d_out, int out_size) {
    const float* inputs = (const float*)d_in[0];
    const float* noise  = (const float*)d_in[1];
    const float* x0     = (const float*)d_in[2];
    const float* Win    = (const float*)d_in[3];
    const float* Wrec   = (const float*)d_in[4];
    const float* brec   = (const float*)d_in[5];
    const float* Wout   = (const float*)d_in[6];
    const float* bout   = (const float*)d_in[7];

    float* outputs = (float*)d_out;                                  // [T,B,NOUT]
    float* states  = (float*)d_out + (size_t)T_STEPS * B_SZ * N_OUT; // [T,B,N]

    uproj_kernel<<<dim3(T_STEPS * B_SZ / 8), dim3(256)>>>(inputs, noise, Win, brec);
    rnn_step_kernel<<<dim3(B_SZ * 2), dim3(256)>>>(x0, Wrec, states);
    rnn_out_kernel<<<dim3(592), dim3(256)>>>(states, Wout, bout, outputs);
}